// round 14
// baseline (speedup 1.0000x reference)
#include <cuda_runtime.h>
#include <cuda_bf16.h>
#include <math.h>
#include <stdint.h>

#define NN 1024
#define BB 32
#define TT 12
#define HORZ 12
#define ROWS (NN*BB)
#define SMEMSZ 65536

// ---------------- static device scratch ----------------
__device__ float g_Sf[2][NN * NN];
__device__ float g_SSf[2][NN * NN];
__device__ float g_rowsum[NN];
__device__ float g_colsum[NN];
__device__ __align__(16) __nv_bfloat16 g_Sh[2][NN * NN];
__device__ __align__(16) __nv_bfloat16 g_Sl[2][NN * NN];
__device__ __align__(16) __nv_bfloat16 g_SSh[2][NN * NN];
__device__ __align__(16) __nv_bfloat16 g_SSl[2][NN * NN];
__device__ __align__(16) __nv_bfloat16 g_Yh[4][NN * 4096];
__device__ __align__(16) __nv_bfloat16 g_Yl[4][NN * 4096];
__device__ __align__(16) __nv_bfloat16 g_Wph[8][640 * 128];
__device__ __align__(16) __nv_bfloat16 g_Wpl[8][640 * 128];
__device__ float g_RU[ROWS * 128];
__device__ float g_h0[ROWS * 64];
__device__ float g_h1[ROWS * 64];
__device__ float g_xdec[ROWS];

// ---------------- helpers ----------------
__device__ __forceinline__ uint32_t smem_u32(const void* p) {
    return (uint32_t)__cvta_generic_to_shared(p);
}
__device__ __forceinline__ void ldsm4(uint32_t* r, uint32_t addr) {
    asm volatile("ldmatrix.sync.aligned.m8n8.x4.shared.b16 {%0,%1,%2,%3}, [%4];"
                 : "=r"(r[0]), "=r"(r[1]), "=r"(r[2]), "=r"(r[3]) : "r"(addr));
}
__device__ __forceinline__ void ldsm4t(uint32_t* r, uint32_t addr) {
    asm volatile("ldmatrix.sync.aligned.m8n8.x4.trans.shared.b16 {%0,%1,%2,%3}, [%4];"
                 : "=r"(r[0]), "=r"(r[1]), "=r"(r[2]), "=r"(r[3]) : "r"(addr));
}
__device__ __forceinline__ void mma16816(float* d, const uint32_t* a, const uint32_t* b) {
    asm volatile("mma.sync.aligned.m16n8k16.row.col.f32.bf16.bf16.f32 "
                 "{%0,%1,%2,%3},{%4,%5,%6,%7},{%8,%9},{%0,%1,%2,%3};"
                 : "+f"(d[0]), "+f"(d[1]), "+f"(d[2]), "+f"(d[3])
                 : "r"(a[0]), "r"(a[1]), "r"(a[2]), "r"(a[3]), "r"(b[0]), "r"(b[1]));
}
__device__ __forceinline__ void cpa16(uint32_t dst, const void* src) {
    asm volatile("cp.async.cg.shared.global [%0], [%1], 16;" :: "r"(dst), "l"(src));
}
#define CPA_COMMIT() asm volatile("cp.async.commit_group;" ::: "memory")
#define CPA_WAIT1()  asm volatile("cp.async.wait_group 1;" ::: "memory")
#define CPA_WAIT0()  asm volatile("cp.async.wait_group 0;" ::: "memory")
__device__ __forceinline__ uint32_t swz(int row, int g) {
    return (uint32_t)(((row << 3) + (g ^ (row & 7))) << 4);
}
union B16x8 { __nv_bfloat16 b[8]; uint4 v; };

// on-the-fly X granule: 8 consecutive f at f0 (f0 % 8 == 0) for row nb.
// Bit-identical to the former concat kernels' values + hi/lo split.
__device__ __forceinline__ void make_xgran(int nb, int f0, int Fx, int xKind,
        int tstep, int useR, const float* __restrict__ hbase,
        const float* __restrict__ src, B16x8* hb, B16x8* lb) {
    float v[8];
    if (f0 < 64) {
        const float4* hp = (const float4*)(hbase + (size_t)nb * 64 + f0);
        float4 a = hp[0], c = hp[1];
        v[0] = a.x; v[1] = a.y; v[2] = a.z; v[3] = a.w;
        v[4] = c.x; v[5] = c.y; v[6] = c.z; v[7] = c.w;
        if (useR) {
            const float4* rp = (const float4*)(g_RU + (size_t)nb * 128 + f0);
            float4 ra = rp[0], rc = rp[1];
            v[0] *= ra.x; v[1] *= ra.y; v[2] *= ra.z; v[3] *= ra.w;
            v[4] *= rc.x; v[5] *= rc.y; v[6] *= rc.z; v[7] *= rc.w;
        }
    } else if (xKind == 1 && f0 + 8 <= 64 + Fx) {
        const float4* xp = (const float4*)(g_h0 + (size_t)nb * 64 + f0 - 64);
        float4 a = xp[0], c = xp[1];
        v[0] = a.x; v[1] = a.y; v[2] = a.z; v[3] = a.w;
        v[4] = c.x; v[5] = c.y; v[6] = c.z; v[7] = c.w;
    } else {
        #pragma unroll
        for (int e = 0; e < 8; e++) {
            int f = f0 + e; float vv = 0.f;
            if (f < 64 + Fx) {
                int xi = f - 64;
                if (xKind == 0) {
                    int n = nb >> 5, b = nb & 31;
                    vv = src[((b * TT + tstep) * NN + n) * 2 + xi];
                } else if (xKind == 1) vv = g_h0[nb * 64 + xi];
                else vv = g_xdec[nb];
            }
            v[e] = vv;
        }
    }
    #pragma unroll
    for (int e = 0; e < 8; e++) {
        __nv_bfloat16 hi = __float2bfloat16(v[e]);
        hb->b[e] = hi;
        lb->b[e] = __float2bfloat16(v[e] - __bfloat162float(hi));
    }
}

// ---------------- init / supports ----------------
__global__ void zero_kernel() {
    int i = blockIdx.x * 256 + threadIdx.x;
    if (i < ROWS * 64) { g_h0[i] = 0.f; g_h1[i] = 0.f; }
    if (i < ROWS) g_xdec[i] = 0.f;
}
__global__ void rowsum_kernel(const float* __restrict__ adj) {
    int n = blockIdx.x;
    float s = 0.f;
    for (int j = threadIdx.x; j < NN; j += 256) s += adj[n * NN + j];
    __shared__ float sh[256];
    sh[threadIdx.x] = s; __syncthreads();
    for (int o = 128; o; o >>= 1) {
        if (threadIdx.x < o) sh[threadIdx.x] += sh[threadIdx.x + o];
        __syncthreads();
    }
    if (threadIdx.x == 0) g_rowsum[n] = sh[0];
}
__global__ void colsum_kernel(const float* __restrict__ adj) {
    int c = blockIdx.x * 256 + threadIdx.x;
    float s = 0.f;
    #pragma unroll 8
    for (int r = 0; r < NN; r++) s += adj[r * NN + c];
    g_colsum[c] = s;
}
__global__ void build_supports(const float* __restrict__ adj) {
    int idx = blockIdx.x * 256 + threadIdx.x;
    int m = idx >> 10, n = idx & 1023;
    g_Sf[0][idx] = adj[n * NN + m] / fmaxf(g_rowsum[n], 1e-8f);
    g_Sf[1][idx] = adj[m * NN + n] / fmaxf(g_colsum[n], 1e-8f);
}
// SS = 2*S*S - I (fp32, one-time)
__global__ __launch_bounds__(256) void ssq_kernel() {
    const float* A = g_Sf[blockIdx.z];
    float* C = g_SSf[blockIdx.z];
    int mb = blockIdx.y * 64, nb = blockIdx.x * 64;
    __shared__ float As[64][17], Bs[16][64];
    int t = threadIdx.x, tx = t & 15, ty = t >> 4;
    float acc[4][4] = {};
    for (int kt = 0; kt < NN; kt += 16) {
        #pragma unroll
        for (int i = 0; i < 4; i++) {
            int e = t + 256 * i;
            As[e >> 4][e & 15] = A[(size_t)(mb + (e >> 4)) * NN + kt + (e & 15)];
        }
        #pragma unroll
        for (int i = 0; i < 4; i++) {
            int e = t + 256 * i;
            Bs[e >> 6][e & 63] = A[(size_t)(kt + (e >> 6)) * NN + nb + (e & 63)];
        }
        __syncthreads();
        #pragma unroll
        for (int k = 0; k < 16; k++) {
            float a[4], b[4];
            #pragma unroll
            for (int i = 0; i < 4; i++) a[i] = As[ty * 4 + i][k];
            #pragma unroll
            for (int j = 0; j < 4; j++) b[j] = Bs[k][tx * 4 + j];
            #pragma unroll
            for (int i = 0; i < 4; i++)
                #pragma unroll
                for (int j = 0; j < 4; j++) acc[i][j] += a[i] * b[j];
        }
        __syncthreads();
    }
    #pragma unroll
    for (int i = 0; i < 4; i++)
        #pragma unroll
        for (int j = 0; j < 4; j++) {
            int m = mb + ty * 4 + i, n = nb + tx * 4 + j;
            C[(size_t)m * NN + n] = 2.f * acc[i][j] - (m == n ? 1.f : 0.f);
        }
}
__global__ void conv_hl(int sel) {
    int idx = blockIdx.x * 256 + threadIdx.x;
    const float* s = (sel < 2) ? g_Sf[sel] : g_SSf[sel - 2];
    __nv_bfloat16* h = (sel < 2) ? g_Sh[sel] : g_SSh[sel - 2];
    __nv_bfloat16* l = (sel < 2) ? g_Sl[sel] : g_SSl[sel - 2];
    float v = s[idx];
    __nv_bfloat16 hi = __float2bfloat16(v);
    h[idx] = hi;
    l[idx] = __float2bfloat16(v - __bfloat162float(hi));
}

// ---------------- W pre-permute/pad, hi/lo ----------------
__global__ void build_wpad(const float* __restrict__ W, int slot, int F, int Fx,
                           int Fpad, int Kpad, int NT) {
    int idx = blockIdx.x * 256 + threadIdx.x;
    if (idx >= Kpad * NT) return;
    int kp = idx / NT, o = idx % NT;
    float v = 0.f;
    if (kp < 5 * Fpad) {
        int blk = kp / Fpad, f = kp - blk * Fpad;
        if (f < 64) v = W[(size_t)(blk * F + Fx + f) * NT + o];
        else if (f < 64 + Fx) v = W[(size_t)(blk * F + f - 64) * NT + o];
    }
    __nv_bfloat16 hi = __float2bfloat16(v);
    g_Wph[slot][idx] = hi;
    g_Wpl[slot][idx] = __float2bfloat16(v - __bfloat162float(hi));
}

// ---------------- diffusion GEMM: Y[z] = M[z] @ X(on-the-fly), both hi/lo, 3 MMAs ----------------
__global__ __launch_bounds__(256, 2) void mm_diffuse(int win, int L, int Fpad,
        int Fx, int xKind, int tstep, int useR, int hsel,
        const float* __restrict__ src) {
    extern __shared__ char sm[];
    const uint32_t sb = smem_u32(sm);
    const int t = threadIdx.x, warp = t >> 5, lane = t & 31;
    const int wm = warp & 3, wn = warp >> 2;
    const int z = blockIdx.z;
    const __nv_bfloat16* Agh = (z & 1) ? g_SSh[z >> 1] : g_Sh[z >> 1];
    const __nv_bfloat16* Agl = (z & 1) ? g_SSl[z >> 1] : g_Sl[z >> 1];
    __nv_bfloat16* Yh = g_Yh[z];
    __nv_bfloat16* Yl = g_Yl[z];
    const int mBase = blockIdx.y * 128;
    const int jt = blockIdx.x;
    const float* hbase = hsel ? g_h1 : g_h0;

    // per-thread B-column mapping (loop-invariant)
    int bcol[2], fcol[2];
    #pragma unroll
    for (int i = 0; i < 2; i++) {
        int gid = t + 256 * i, gc = gid & 15;
        int j = win ? ((jt * 2 + (gc >> 3)) * Fpad + (gc & 7) * 8)
                    : (jt * 128 + gc * 8);
        bcol[i] = j / Fpad; fcol[i] = j % Fpad;
    }

    float acc[2][8][4];
    #pragma unroll
    for (int a = 0; a < 2; a++)
        #pragma unroll
        for (int b = 0; b < 8; b++)
            #pragma unroll
            for (int c = 0; c < 4; c++) acc[a][b][c] = 0.f;

    auto stageA = [&](int kc, int s) {
        #pragma unroll
        for (int i = 0; i < 2; i++) {
            int gid = t + 256 * i;
            int r = gid >> 2, g = gid & 3;
            size_t gi = (size_t)(mBase + r) * NN + kc * 32 + g * 8;
            uint32_t off = (uint32_t)(((r << 3) + ((s * 4 + g) ^ (r & 7))) << 4);
            cpa16(sb + off, Agh + gi);
            cpa16(sb + 16384 + off, Agl + gi);
        }
    };
    auto stageB = [&](int kc, int s) {
        #pragma unroll
        for (int i = 0; i < 2; i++) {
            int gid = t + 256 * i;
            int r = gid >> 4, gc = gid & 15;
            int nb = (kc * 32 + r) * 32 + bcol[i];
            B16x8 hb, lb;
            make_xgran(nb, fcol[i], Fx, xKind, tstep, useR, hbase, src, &hb, &lb);
            uint32_t off = 32768 + (gc >> 3) * 8192 + swz(32 * s + r, gc & 7);
            *(uint4*)(sm + off) = hb.v;
            *(uint4*)(sm + off + 16384) = lb.v;
        }
    };
    auto compute = [&](int s) {
        uint32_t aH = sb, aL = sb + 16384;
        uint32_t bH = sb + 32768 + wn * 8192, bL = bH + 16384;
        #pragma unroll
        for (int ks = 0; ks < 32; ks += 16) {
            uint32_t a_h[2][4], a_l[2][4];
            #pragma unroll
            for (int ms = 0; ms < 2; ms++) {
                int row = wm * 32 + ms * 16 + (lane & 15);
                int gg = s * 4 + (ks >> 3) + (lane >> 4);
                uint32_t off = (uint32_t)(((row << 3) + (gg ^ (row & 7))) << 4);
                ldsm4(a_h[ms], aH + off);
                ldsm4(a_l[ms], aL + off);
            }
            uint32_t b_h[8][2], b_l[8][2];
            #pragma unroll
            for (int nf = 0; nf < 4; nf++) {
                uint32_t off = swz(32 * s + ks + (lane & 15), nf * 2 + (lane >> 4));
                uint32_t r4[4];
                ldsm4t(r4, bH + off);
                b_h[2 * nf][0] = r4[0]; b_h[2 * nf][1] = r4[1];
                b_h[2 * nf + 1][0] = r4[2]; b_h[2 * nf + 1][1] = r4[3];
                ldsm4t(r4, bL + off);
                b_l[2 * nf][0] = r4[0]; b_l[2 * nf][1] = r4[1];
                b_l[2 * nf + 1][0] = r4[2]; b_l[2 * nf + 1][1] = r4[3];
            }
            #pragma unroll
            for (int ms = 0; ms < 2; ms++)
                #pragma unroll
                for (int n8 = 0; n8 < 8; n8++) {
                    mma16816(acc[ms][n8], a_h[ms], b_h[n8]);
                    mma16816(acc[ms][n8], a_h[ms], b_l[n8]);
                    mma16816(acc[ms][n8], a_l[ms], b_h[n8]);
                }
        }
    };

    stageA(0, 0); stageB(0, 0); CPA_COMMIT();
    for (int kc = 0; kc < 32; kc++) {
        if (kc < 31) {
            stageA(kc + 1, (kc + 1) & 1); stageB(kc + 1, (kc + 1) & 1);
            CPA_COMMIT(); CPA_WAIT1();
        } else CPA_WAIT0();
        __syncthreads();
        compute(kc & 1);
        __syncthreads();
    }

    #pragma unroll
    for (int ms = 0; ms < 2; ms++)
        #pragma unroll
        for (int n8 = 0; n8 < 8; n8++) {
            int col = wn * 64 + n8 * 8 + (lane & 3) * 2;
            int j = win ? ((jt * 2 + (col >> 6)) * Fpad + (col & 63))
                        : (jt * 128 + col);
            #pragma unroll
            for (int half = 0; half < 2; half++) {
                int m = mBase + wm * 32 + ms * 16 + (lane >> 2) + half * 8;
                float v0 = acc[ms][n8][half * 2], v1 = acc[ms][n8][half * 2 + 1];
                __nv_bfloat162 hv, lv;
                hv.x = __float2bfloat16(v0); hv.y = __float2bfloat16(v1);
                lv.x = __float2bfloat16(v0 - __bfloat162float(hv.x));
                lv.y = __float2bfloat16(v1 - __bfloat162float(hv.y));
                *(__nv_bfloat162*)(Yh + (size_t)m * L + j) = hv;
                *(__nv_bfloat162*)(Yl + (size_t)m * L + j) = lv;
            }
        }
}

// ---------------- W projection: Z(on-the-fly X | Y) @ W(hi/lo), 3 MMAs, fused GRU ----------------
template<int NT>
__global__ __launch_bounds__(256, 2) void mm_w(int slot, const float* __restrict__ bias,
        int Fpad, int KC, int mode, int hsel,
        int Fx, int xKind, int tstep, const float* __restrict__ src) {
    extern __shared__ char sm[];
    const uint32_t sb = smem_u32(sm);
    const int t = threadIdx.x, warp = t >> 5, lane = t & 31;
    const int wm = warp & 3, wn = warp >> 2;
    const int rBase = blockIdx.x * 128;
    const __nv_bfloat16* Wh = g_Wph[slot];
    const __nv_bfloat16* Wl = g_Wpl[slot];
    const float* hbase = hsel ? g_h1 : g_h0;
    const int F5 = 5 * Fpad;
    constexpr int N8 = NT / 16, NF = NT / 32, BG2 = NT / 64;
    constexpr uint32_t BL = (NT == 128) ? 16384 : 8192;

    float acc[2][N8][4];
    #pragma unroll
    for (int a = 0; a < 2; a++)
        #pragma unroll
        for (int b = 0; b < N8; b++)
            #pragma unroll
            for (int c = 0; c < 4; c++) acc[a][b][c] = 0.f;

    auto stage = [&](int kc, int s) {
        #pragma unroll
        for (int i = 0; i < 2; i++) {           // A: Z gather, 128r x 4 granules hi+lo
            int gid = t + 256 * i;
            int r = gid >> 2, g = gid & 3;
            int kp = kc * 32 + g * 8;
            uint32_t off = (uint32_t)(((r << 3) + ((s * 4 + g) ^ (r & 7))) << 4);
            if (kp < Fpad) {
                // block 0 = X on the fly (mode doubles as useR: c-phase uses r*h)
                B16x8 hb, lb;
                make_xgran(rBase + r, kp, Fx, xKind, tstep, mode, hbase, src, &hb, &lb);
                *(uint4*)(sm + off) = hb.v;
                *(uint4*)(sm + off + 16384) = lb.v;
            } else if (kp < F5) {
                int blk = kp / Fpad, f = kp - blk * Fpad;
                size_t gi = (size_t)(rBase + r) * Fpad + f;
                cpa16(sb + off, g_Yh[blk - 1] + gi);
                cpa16(sb + 16384 + off, g_Yl[blk - 1] + gi);
            } else {
                *(uint4*)(sm + off) = make_uint4(0, 0, 0, 0);
                *(uint4*)(sm + off + 16384) = make_uint4(0, 0, 0, 0);
            }
        }
        #pragma unroll
        for (int i = 0; i < BG2; i++) {         // B: W, 32 k-rows x NT cols hi+lo
            int gid = t + 256 * i;
            int r, gc;
            if (NT == 128) { r = gid >> 4; gc = gid & 15; }
            else           { r = gid >> 3; gc = gid & 7; }
            size_t gi = (size_t)(kc * 32 + r) * NT + gc * 8;
            uint32_t d = sb + 32768 + (gc >> 3) * 8192 + swz(32 * s + r, gc & 7);
            cpa16(d, Wh + gi);
            cpa16(d + BL, Wl + gi);
        }
    };
    auto compute = [&](int s) {
        uint32_t aH = sb, aL = sb + 16384;
        #pragma unroll
        for (int ks = 0; ks < 32; ks += 16) {
            uint32_t a_h[2][4], a_l[2][4];
            #pragma unroll
            for (int ms = 0; ms < 2; ms++) {
                int row = wm * 32 + ms * 16 + (lane & 15);
                int gg = s * 4 + (ks >> 3) + (lane >> 4);
                uint32_t off = (uint32_t)(((row << 3) + (gg ^ (row & 7))) << 4);
                ldsm4(a_h[ms], aH + off);
                ldsm4(a_l[ms], aL + off);
            }
            uint32_t b_h[N8][2], b_l[N8][2];
            #pragma unroll
            for (int nf = 0; nf < NF; nf++) {
                int G = wn * (NT / 16) + nf * 2 + (lane >> 4);
                uint32_t off = sb + 32768 + (G >> 3) * 8192 + swz(32 * s + ks + (lane & 15), G & 7);
                uint32_t r4[4];
                ldsm4t(r4, off);
                b_h[2 * nf][0] = r4[0]; b_h[2 * nf][1] = r4[1];
                b_h[2 * nf + 1][0] = r4[2]; b_h[2 * nf + 1][1] = r4[3];
                ldsm4t(r4, off + BL);
                b_l[2 * nf][0] = r4[0]; b_l[2 * nf][1] = r4[1];
                b_l[2 * nf + 1][0] = r4[2]; b_l[2 * nf + 1][1] = r4[3];
            }
            #pragma unroll
            for (int ms = 0; ms < 2; ms++)
                #pragma unroll
                for (int n8 = 0; n8 < N8; n8++) {
                    mma16816(acc[ms][n8], a_h[ms], b_h[n8]);
                    mma16816(acc[ms][n8], a_h[ms], b_l[n8]);
                    mma16816(acc[ms][n8], a_l[ms], b_h[n8]);
                }
        }
    };

    stage(0, 0); CPA_COMMIT();
    for (int kc = 0; kc < KC; kc++) {
        if (kc < KC - 1) { stage(kc + 1, (kc + 1) & 1); CPA_COMMIT(); CPA_WAIT1(); }
        else CPA_WAIT0();
        __syncthreads();
        compute(kc & 1);
        __syncthreads();
    }

    float* hb = hsel ? g_h1 : g_h0;
    #pragma unroll
    for (int ms = 0; ms < 2; ms++)
        #pragma unroll
        for (int n8 = 0; n8 < N8; n8++) {
            int col = wn * (NT / 2) + n8 * 8 + (lane & 3) * 2;
            #pragma unroll
            for (int half = 0; half < 2; half++) {
                int r = rBase + wm * 32 + ms * 16 + (lane >> 2) + half * 8;
                float v0 = acc[ms][n8][half * 2] + bias[col];
                float v1 = acc[ms][n8][half * 2 + 1] + bias[col + 1];
                if (mode == 0) {
                    float2 o = make_float2(1.f / (1.f + expf(-v0)),
                                           1.f / (1.f + expf(-v1)));
                    *(float2*)(g_RU + (size_t)r * 128 + col) = o;
                } else {
                    float u0 = g_RU[(size_t)r * 128 + 64 + col];
                    float u1 = g_RU[(size_t)r * 128 + 64 + col + 1];
                    float h0v = hb[(size_t)r * 64 + col];
                    float h1v = hb[(size_t)r * 64 + col + 1];
                    float2 o = make_float2(u0 * h0v + (1.f - u0) * tanhf(v0),
                                           u1 * h1v + (1.f - u1) * tanhf(v1));
                    *(float2*)(hb + (size_t)r * 64 + col) = o;
                }
            }
        }
}

// ---------------- output projection + decoder feedback ----------------
__global__ void fcn_kernel(const float* __restrict__ fcnW,
                           const float* __restrict__ fcnb,
                           float* __restrict__ out) {
    int w = (blockIdx.x * blockDim.x + threadIdx.x) >> 5;
    int lane = threadIdx.x & 31;
    if (w >= ROWS) return;
    const float* hr = g_h1 + (size_t)w * 64;
    float s = hr[lane] * fcnW[lane] + hr[lane + 32] * fcnW[lane + 32];
    #pragma unroll
    for (int off = 16; off; off >>= 1) s += __shfl_down_sync(0xffffffffu, s, off);
    if (lane == 0) {
        int n = w >> 5, b = w & 31;
        float v = s + fcnb[0];
        out[b * NN + n] = v;
        g_xdec[w] = v;
    }
}

// ---------------- host ----------------
static void run_cell(const float* src, int xKind, int tstep, int Fx, int hsel,
                     int slotRu, int slotC, const float* bru, const float* bc,
                     int Fpad, int KC) {
    int L = 32 * Fpad;
    mm_diffuse<<<dim3(L / 128, 8, 4), 256, SMEMSZ>>>(0, L, Fpad, Fx, xKind, tstep, 0, hsel, src);
    mm_w<128><<<256, 256, SMEMSZ>>>(slotRu, bru, Fpad, KC, 0, hsel, Fx, xKind, tstep, src);
    mm_diffuse<<<dim3(16, 8, 4), 256, SMEMSZ>>>(1, L, Fpad, Fx, xKind, tstep, 1, hsel, src);
    mm_w<64><<<256, 256, 49152>>>(slotC, bc, Fpad, KC, 1, hsel, Fx, xKind, tstep, src);
}

extern "C" void kernel_launch(void* const* d_in, const int* in_sizes, int n_in,
                              void* d_out, int out_size) {
    (void)in_sizes; (void)n_in; (void)out_size;
    const float* adj    = (const float*)d_in[0];
    const float* source = (const float*)d_in[1];
    const float* W[8]   = {(const float*)d_in[3],  (const float*)d_in[5],
                           (const float*)d_in[7],  (const float*)d_in[9],
                           (const float*)d_in[11], (const float*)d_in[13],
                           (const float*)d_in[15], (const float*)d_in[17]};
    const float* B[8]   = {(const float*)d_in[4],  (const float*)d_in[6],
                           (const float*)d_in[8],  (const float*)d_in[10],
                           (const float*)d_in[12], (const float*)d_in[14],
                           (const float*)d_in[16], (const float*)d_in[18]};
    const float* fcnW = (const float*)d_in[19];
    const float* fcnb = (const float*)d_in[20];
    float* out = (float*)d_out;

    cudaFuncSetAttribute(mm_diffuse, cudaFuncAttributeMaxDynamicSharedMemorySize, SMEMSZ);
    cudaFuncSetAttribute(mm_w<128>, cudaFuncAttributeMaxDynamicSharedMemorySize, SMEMSZ);
    cudaFuncSetAttribute(mm_w<64>, cudaFuncAttributeMaxDynamicSharedMemorySize, 49152);

    zero_kernel<<<8192, 256>>>();
    rowsum_kernel<<<NN, 256>>>(adj);
    colsum_kernel<<<4, 256>>>(adj);
    build_supports<<<4096, 256>>>(adj);
    ssq_kernel<<<dim3(16, 16, 2), 256>>>();
    for (int s = 0; s < 4; s++) conv_hl<<<4096, 256>>>(s);

    const int cF[4]  = {66, 128, 65, 128};
    const int cFx[4] = {2, 64, 1, 64};
    const int cFp[4] = {72, 128, 72, 128};
    const int cKp[4] = {384, 640, 384, 640};
    for (int c = 0; c < 4; c++) {
        build_wpad<<<(cKp[c] * 128 + 255) / 256, 256>>>(W[c * 2],     c * 2,     cF[c], cFx[c], cFp[c], cKp[c], 128);
        build_wpad<<<(cKp[c] * 64  + 255) / 256, 256>>>(W[c * 2 + 1], c * 2 + 1, cF[c], cFx[c], cFp[c], cKp[c], 64);
    }

    for (int t = 0; t < TT; t++) {
        run_cell(source, 0, t, 2, 0, 0, 1, B[0], B[1], 72, 12);
        run_cell(source, 1, 0, 64, 1, 2, 3, B[2], B[3], 128, 20);
    }
    for (int t = 0; t < HORZ; t++) {
        run_cell(source, 2, 0, 1, 0, 4, 5, B[4], B[5], 72, 12);
        run_cell(source, 1, 0, 64, 1, 6, 7, B[6], B[7], 128, 20);
        fcn_kernel<<<4096, 256>>>(fcnW, fcnb, out + t * BB * NN);
    }
}

// round 15
// speedup vs baseline: 1.1866x; 1.1866x over previous
#include <cuda_runtime.h>
#include <cuda_bf16.h>
#include <math.h>
#include <stdint.h>

#define NN 1024
#define BB 32
#define TT 12
#define HORZ 12
#define ROWS (NN*BB)
#define SMEMSZ 65536

// ---------------- static device scratch ----------------
__device__ float g_Sf[2][NN * NN];
__device__ float g_rowsum[NN];
__device__ float g_colsum[NN];
__device__ __align__(16) __nv_bfloat16 g_Sh[2][NN * NN];
__device__ __align__(16) __nv_bfloat16 g_Sl[2][NN * NN];
__device__ __align__(16) __nv_bfloat16 g_SSh[2][NN * NN];
__device__ __align__(16) __nv_bfloat16 g_SSl[2][NN * NN];
__device__ __align__(16) __nv_bfloat16 g_Xh[NN * 4096];
__device__ __align__(16) __nv_bfloat16 g_Xl[NN * 4096];
__device__ __align__(16) __nv_bfloat16 g_Yh[4][NN * 4096];
__device__ __align__(16) __nv_bfloat16 g_Yl[4][NN * 4096];
__device__ __align__(16) __nv_bfloat16 g_Wph[8][640 * 128];
__device__ __align__(16) __nv_bfloat16 g_Wpl[8][640 * 128];
__device__ float g_RU[ROWS * 128];
__device__ float g_h0[ROWS * 64];
__device__ float g_h1[ROWS * 64];
__device__ float g_xdec[ROWS];

// ---------------- helpers ----------------
__device__ __forceinline__ uint32_t smem_u32(const void* p) {
    return (uint32_t)__cvta_generic_to_shared(p);
}
__device__ __forceinline__ void ldsm4(uint32_t* r, uint32_t addr) {
    asm volatile("ldmatrix.sync.aligned.m8n8.x4.shared.b16 {%0,%1,%2,%3}, [%4];"
                 : "=r"(r[0]), "=r"(r[1]), "=r"(r[2]), "=r"(r[3]) : "r"(addr));
}
__device__ __forceinline__ void ldsm4t(uint32_t* r, uint32_t addr) {
    asm volatile("ldmatrix.sync.aligned.m8n8.x4.trans.shared.b16 {%0,%1,%2,%3}, [%4];"
                 : "=r"(r[0]), "=r"(r[1]), "=r"(r[2]), "=r"(r[3]) : "r"(addr));
}
__device__ __forceinline__ void mma16816(float* d, const uint32_t* a, const uint32_t* b) {
    asm volatile("mma.sync.aligned.m16n8k16.row.col.f32.bf16.bf16.f32 "
                 "{%0,%1,%2,%3},{%4,%5,%6,%7},{%8,%9},{%0,%1,%2,%3};"
                 : "+f"(d[0]), "+f"(d[1]), "+f"(d[2]), "+f"(d[3])
                 : "r"(a[0]), "r"(a[1]), "r"(a[2]), "r"(a[3]), "r"(b[0]), "r"(b[1]));
}
__device__ __forceinline__ void cpa16(uint32_t dst, const void* src) {
    asm volatile("cp.async.cg.shared.global [%0], [%1], 16;" :: "r"(dst), "l"(src));
}
#define CPA_COMMIT() asm volatile("cp.async.commit_group;" ::: "memory")
#define CPA_WAIT1()  asm volatile("cp.async.wait_group 1;" ::: "memory")
#define CPA_WAIT0()  asm volatile("cp.async.wait_group 0;" ::: "memory")
__device__ __forceinline__ uint32_t swz(int row, int g) {
    return (uint32_t)(((row << 3) + (g ^ (row & 7))) << 4);
}

// ---------------- init / supports ----------------
__global__ void zero_kernel() {
    int i = blockIdx.x * 256 + threadIdx.x;
    if (i < ROWS * 64) { g_h0[i] = 0.f; g_h1[i] = 0.f; }
    if (i < ROWS) g_xdec[i] = 0.f;
}
__global__ void rowsum_kernel(const float* __restrict__ adj) {
    int n = blockIdx.x;
    float s = 0.f;
    for (int j = threadIdx.x; j < NN; j += 256) s += adj[n * NN + j];
    __shared__ float sh[256];
    sh[threadIdx.x] = s; __syncthreads();
    for (int o = 128; o; o >>= 1) {
        if (threadIdx.x < o) sh[threadIdx.x] += sh[threadIdx.x + o];
        __syncthreads();
    }
    if (threadIdx.x == 0) g_rowsum[n] = sh[0];
}
__global__ void colsum_kernel(const float* __restrict__ adj) {
    int c = blockIdx.x * 256 + threadIdx.x;
    float s = 0.f;
    #pragma unroll 8
    for (int r = 0; r < NN; r++) s += adj[r * NN + c];
    g_colsum[c] = s;
}
__global__ void build_supports(const float* __restrict__ adj) {
    int idx = blockIdx.x * 256 + threadIdx.x;
    int m = idx >> 10, n = idx & 1023;
    g_Sf[0][idx] = adj[n * NN + m] / fmaxf(g_rowsum[n], 1e-8f);
    g_Sf[1][idx] = adj[m * NN + n] / fmaxf(g_colsum[n], 1e-8f);
}
__global__ void conv_hl(int sel) {
    int idx = blockIdx.x * 256 + threadIdx.x;
    float v = g_Sf[sel][idx];
    __nv_bfloat16 hi = __float2bfloat16(v);
    g_Sh[sel][idx] = hi;
    g_Sl[sel][idx] = __float2bfloat16(v - __bfloat162float(hi));
}

// ---------------- tensor-core SS = 2*S@S - I, fused hi/lo output ----------------
// Clone of mm_diffuse's pipeline: A = S (hi/lo, rows mBase..), B = S (hi/lo, rows k, cols jt*128..)
__global__ __launch_bounds__(256, 2) void ssq_tc() {
    extern __shared__ char sm[];
    const uint32_t sb = smem_u32(sm);
    const int t = threadIdx.x, warp = t >> 5, lane = t & 31;
    const int wm = warp & 3, wn = warp >> 2;
    const int z = blockIdx.z;
    const __nv_bfloat16* Sh = g_Sh[z];
    const __nv_bfloat16* Sl = g_Sl[z];
    const int mBase = blockIdx.y * 128;
    const int jt = blockIdx.x;

    float acc[2][8][4];
    #pragma unroll
    for (int a = 0; a < 2; a++)
        #pragma unroll
        for (int b = 0; b < 8; b++)
            #pragma unroll
            for (int c = 0; c < 4; c++) acc[a][b][c] = 0.f;

    auto stage = [&](int kc, int s) {
        #pragma unroll
        for (int i = 0; i < 2; i++) {           // A: 128r x 4 granules, hi+lo
            int gid = t + 256 * i;
            int r = gid >> 2, g = gid & 3;
            size_t gi = (size_t)(mBase + r) * NN + kc * 32 + g * 8;
            uint32_t off = (uint32_t)(((r << 3) + ((s * 4 + g) ^ (r & 7))) << 4);
            cpa16(sb + off, Sh + gi);
            cpa16(sb + 16384 + off, Sl + gi);
        }
        #pragma unroll
        for (int i = 0; i < 2; i++) {           // B: 32 k-rows x 16 granules, hi+lo
            int gid = t + 256 * i;
            int r = gid >> 4, gc = gid & 15;
            size_t gi = (size_t)(kc * 32 + r) * NN + jt * 128 + gc * 8;
            uint32_t d = sb + 32768 + (gc >> 3) * 8192 + swz(32 * s + r, gc & 7);
            cpa16(d, Sh + gi);
            cpa16(d + 16384, Sl + gi);
        }
    };
    auto compute = [&](int s) {
        uint32_t aH = sb, aL = sb + 16384;
        uint32_t bH = sb + 32768 + wn * 8192, bL = bH + 16384;
        #pragma unroll
        for (int ks = 0; ks < 32; ks += 16) {
            uint32_t a_h[2][4], a_l[2][4];
            #pragma unroll
            for (int ms = 0; ms < 2; ms++) {
                int row = wm * 32 + ms * 16 + (lane & 15);
                int gg = s * 4 + (ks >> 3) + (lane >> 4);
                uint32_t off = (uint32_t)(((row << 3) + (gg ^ (row & 7))) << 4);
                ldsm4(a_h[ms], aH + off);
                ldsm4(a_l[ms], aL + off);
            }
            uint32_t b_h[8][2], b_l[8][2];
            #pragma unroll
            for (int nf = 0; nf < 4; nf++) {
                uint32_t off = swz(32 * s + ks + (lane & 15), nf * 2 + (lane >> 4));
                uint32_t r4[4];
                ldsm4t(r4, bH + off);
                b_h[2 * nf][0] = r4[0]; b_h[2 * nf][1] = r4[1];
                b_h[2 * nf + 1][0] = r4[2]; b_h[2 * nf + 1][1] = r4[3];
                ldsm4t(r4, bL + off);
                b_l[2 * nf][0] = r4[0]; b_l[2 * nf][1] = r4[1];
                b_l[2 * nf + 1][0] = r4[2]; b_l[2 * nf + 1][1] = r4[3];
            }
            #pragma unroll
            for (int ms = 0; ms < 2; ms++)
                #pragma unroll
                for (int n8 = 0; n8 < 8; n8++) {
                    mma16816(acc[ms][n8], a_h[ms], b_h[n8]);
                    mma16816(acc[ms][n8], a_h[ms], b_l[n8]);
                    mma16816(acc[ms][n8], a_l[ms], b_h[n8]);
                }
        }
    };

    stage(0, 0); CPA_COMMIT();
    for (int kc = 0; kc < 32; kc++) {
        if (kc < 31) { stage(kc + 1, (kc + 1) & 1); CPA_COMMIT(); CPA_WAIT1(); }
        else CPA_WAIT0();
        __syncthreads();
        compute(kc & 1);
        __syncthreads();
    }

    #pragma unroll
    for (int ms = 0; ms < 2; ms++)
        #pragma unroll
        for (int n8 = 0; n8 < 8; n8++) {
            int col = wn * 64 + n8 * 8 + (lane & 3) * 2;
            int j = jt * 128 + col;
            #pragma unroll
            for (int half = 0; half < 2; half++) {
                int m = mBase + wm * 32 + ms * 16 + (lane >> 2) + half * 8;
                float v0 = 2.f * acc[ms][n8][half * 2]     - ((m == j)     ? 1.f : 0.f);
                float v1 = 2.f * acc[ms][n8][half * 2 + 1] - ((m == j + 1) ? 1.f : 0.f);
                __nv_bfloat162 hv, lv;
                hv.x = __float2bfloat16(v0); hv.y = __float2bfloat16(v1);
                lv.x = __float2bfloat16(v0 - __bfloat162float(hv.x));
                lv.y = __float2bfloat16(v1 - __bfloat162float(hv.y));
                *(__nv_bfloat162*)(g_SSh[z] + (size_t)m * NN + j) = hv;
                *(__nv_bfloat162*)(g_SSl[z] + (size_t)m * NN + j) = lv;
            }
        }
}

// ---------------- W pre-permute/pad, hi/lo ----------------
__global__ void build_wpad(const float* __restrict__ W, int slot, int F, int Fx,
                           int Fpad, int Kpad, int NT) {
    int idx = blockIdx.x * 256 + threadIdx.x;
    if (idx >= Kpad * NT) return;
    int kp = idx / NT, o = idx % NT;
    float v = 0.f;
    if (kp < 5 * Fpad) {
        int blk = kp / Fpad, f = kp - blk * Fpad;
        if (f < 64) v = W[(size_t)(blk * F + Fx + f) * NT + o];
        else if (f < 64 + Fx) v = W[(size_t)(blk * F + f - 64) * NT + o];
    }
    __nv_bfloat16 hi = __float2bfloat16(v);
    g_Wph[slot][idx] = hi;
    g_Wpl[slot][idx] = __float2bfloat16(v - __bfloat162float(hi));
}

// ---------------- concat: build X (bf16 hi/lo), layout [h|x|pad] ----------------
__global__ void concat_full(const float* __restrict__ src, int Fpad, int Fx,
                            int xKind, int tstep, int hsel) {
    int idx = blockIdx.x * 256 + threadIdx.x;
    if (idx >= ROWS * Fpad) return;
    int f = idx % Fpad, nb = idx / Fpad;
    float v = 0.f;
    if (f < 64) v = (hsel ? g_h1 : g_h0)[nb * 64 + f];
    else if (f < 64 + Fx) {
        int xi = f - 64;
        if (xKind == 0) { int n = nb >> 5, b = nb & 31; v = src[((b * TT + tstep) * NN + n) * 2 + xi]; }
        else if (xKind == 1) v = g_h0[nb * 64 + xi];
        else v = g_xdec[nb];
    }
    __nv_bfloat16 hi = __float2bfloat16(v);
    g_Xh[idx] = hi;
    g_Xl[idx] = __float2bfloat16(v - __bfloat162float(hi));
}
__global__ void concat_rh(int Fpad, int hsel) {
    int idx = blockIdx.x * 256 + threadIdx.x;
    if (idx >= ROWS * 64) return;
    int f = idx & 63, nb = idx >> 6;
    float v = (hsel ? g_h1 : g_h0)[idx] * g_RU[nb * 128 + f];
    __nv_bfloat16 hi = __float2bfloat16(v);
    g_Xh[(size_t)nb * Fpad + f] = hi;
    g_Xl[(size_t)nb * Fpad + f] = __float2bfloat16(v - __bfloat162float(hi));
}

// ---------------- diffusion GEMM: Y[z] = M[z] @ X, both hi/lo, 3 MMAs ----------------
__global__ __launch_bounds__(256, 2) void mm_diffuse(int win, int L, int Fpad) {
    extern __shared__ char sm[];
    const uint32_t sb = smem_u32(sm);
    const int t = threadIdx.x, warp = t >> 5, lane = t & 31;
    const int wm = warp & 3, wn = warp >> 2;
    const int z = blockIdx.z;
    const __nv_bfloat16* Agh = (z & 1) ? g_SSh[z >> 1] : g_Sh[z >> 1];
    const __nv_bfloat16* Agl = (z & 1) ? g_SSl[z >> 1] : g_Sl[z >> 1];
    __nv_bfloat16* Yh = g_Yh[z];
    __nv_bfloat16* Yl = g_Yl[z];
    const int mBase = blockIdx.y * 128;
    const int jt = blockIdx.x;

    float acc[2][8][4];
    #pragma unroll
    for (int a = 0; a < 2; a++)
        #pragma unroll
        for (int b = 0; b < 8; b++)
            #pragma unroll
            for (int c = 0; c < 4; c++) acc[a][b][c] = 0.f;

    auto stage = [&](int kc, int s) {
        #pragma unroll
        for (int i = 0; i < 2; i++) {           // A: 128r x 4 granules, hi+lo
            int gid = t + 256 * i;
            int r = gid >> 2, g = gid & 3;
            size_t gi = (size_t)(mBase + r) * NN + kc * 32 + g * 8;
            uint32_t off = (uint32_t)(((r << 3) + ((s * 4 + g) ^ (r & 7))) << 4);
            cpa16(sb + off, Agh + gi);
            cpa16(sb + 16384 + off, Agl + gi);
        }
        #pragma unroll
        for (int i = 0; i < 2; i++) {           // B: 32 k-rows x 16 granules, hi+lo
            int gid = t + 256 * i;
            int r = gid >> 4, gc = gid & 15;
            int j = win ? ((jt * 2 + (gc >> 3)) * Fpad + (gc & 7) * 8)
                        : (jt * 128 + gc * 8);
            size_t gi = (size_t)(kc * 32 + r) * L + j;
            uint32_t d = sb + 32768 + (gc >> 3) * 8192 + swz(32 * s + r, gc & 7);
            cpa16(d, g_Xh + gi);
            cpa16(d + 16384, g_Xl + gi);
        }
    };
    auto compute = [&](int s) {
        uint32_t aH = sb, aL = sb + 16384;
        uint32_t bH = sb + 32768 + wn * 8192, bL = bH + 16384;
        #pragma unroll
        for (int ks = 0; ks < 32; ks += 16) {
            uint32_t a_h[2][4], a_l[2][4];
            #pragma unroll
            for (int ms = 0; ms < 2; ms++) {
                int row = wm * 32 + ms * 16 + (lane & 15);
                int gg = s * 4 + (ks >> 3) + (lane >> 4);
                uint32_t off = (uint32_t)(((row << 3) + (gg ^ (row & 7))) << 4);
                ldsm4(a_h[ms], aH + off);
                ldsm4(a_l[ms], aL + off);
            }
            uint32_t b_h[8][2], b_l[8][2];
            #pragma unroll
            for (int nf = 0; nf < 4; nf++) {
                uint32_t off = swz(32 * s + ks + (lane & 15), nf * 2 + (lane >> 4));
                uint32_t r4[4];
                ldsm4t(r4, bH + off);
                b_h[2 * nf][0] = r4[0]; b_h[2 * nf][1] = r4[1];
                b_h[2 * nf + 1][0] = r4[2]; b_h[2 * nf + 1][1] = r4[3];
                ldsm4t(r4, bL + off);
                b_l[2 * nf][0] = r4[0]; b_l[2 * nf][1] = r4[1];
                b_l[2 * nf + 1][0] = r4[2]; b_l[2 * nf + 1][1] = r4[3];
            }
            #pragma unroll
            for (int ms = 0; ms < 2; ms++)
                #pragma unroll
                for (int n8 = 0; n8 < 8; n8++) {
                    mma16816(acc[ms][n8], a_h[ms], b_h[n8]);
                    mma16816(acc[ms][n8], a_h[ms], b_l[n8]);
                    mma16816(acc[ms][n8], a_l[ms], b_h[n8]);
                }
        }
    };

    stage(0, 0); CPA_COMMIT();
    for (int kc = 0; kc < 32; kc++) {
        if (kc < 31) { stage(kc + 1, (kc + 1) & 1); CPA_COMMIT(); CPA_WAIT1(); }
        else CPA_WAIT0();
        __syncthreads();
        compute(kc & 1);
        __syncthreads();
    }

    #pragma unroll
    for (int ms = 0; ms < 2; ms++)
        #pragma unroll
        for (int n8 = 0; n8 < 8; n8++) {
            int col = wn * 64 + n8 * 8 + (lane & 3) * 2;
            int j = win ? ((jt * 2 + (col >> 6)) * Fpad + (col & 63))
                        : (jt * 128 + col);
            #pragma unroll
            for (int half = 0; half < 2; half++) {
                int m = mBase + wm * 32 + ms * 16 + (lane >> 2) + half * 8;
                float v0 = acc[ms][n8][half * 2], v1 = acc[ms][n8][half * 2 + 1];
                __nv_bfloat162 hv, lv;
                hv.x = __float2bfloat16(v0); hv.y = __float2bfloat16(v1);
                lv.x = __float2bfloat16(v0 - __bfloat162float(hv.x));
                lv.y = __float2bfloat16(v1 - __bfloat162float(hv.y));
                *(__nv_bfloat162*)(Yh + (size_t)m * L + j) = hv;
                *(__nv_bfloat162*)(Yl + (size_t)m * L + j) = lv;
            }
        }
}

// ---------------- W projection: Z(hi/lo) @ W(hi/lo), 3 MMAs, fused GRU epilogue ----------------
template<int NT>
__global__ __launch_bounds__(256, 2) void mm_w(int slot, const float* __restrict__ bias,
                                               int Fpad, int KC, int mode, int hsel) {
    extern __shared__ char sm[];
    const uint32_t sb = smem_u32(sm);
    const int t = threadIdx.x, warp = t >> 5, lane = t & 31;
    const int wm = warp & 3, wn = warp >> 2;
    const int rBase = blockIdx.x * 128;
    const __nv_bfloat16* Wh = g_Wph[slot];
    const __nv_bfloat16* Wl = g_Wpl[slot];
    const int F5 = 5 * Fpad;
    constexpr int N8 = NT / 16, NF = NT / 32, BG2 = NT / 64;
    constexpr uint32_t BL = (NT == 128) ? 16384 : 8192;

    float acc[2][N8][4];
    #pragma unroll
    for (int a = 0; a < 2; a++)
        #pragma unroll
        for (int b = 0; b < N8; b++)
            #pragma unroll
            for (int c = 0; c < 4; c++) acc[a][b][c] = 0.f;

    auto stage = [&](int kc, int s) {
        #pragma unroll
        for (int i = 0; i < 2; i++) {           // A: Z gather, 128r x 4 granules hi+lo
            int gid = t + 256 * i;
            int r = gid >> 2, g = gid & 3;
            int kp = kc * 32 + g * 8;
            uint32_t off = (uint32_t)(((r << 3) + ((s * 4 + g) ^ (r & 7))) << 4);
            if (kp < F5) {
                int blk = kp / Fpad, f = kp - blk * Fpad;
                const __nv_bfloat16* shp = (blk == 0) ? g_Xh : g_Yh[blk - 1];
                const __nv_bfloat16* slp = (blk == 0) ? g_Xl : g_Yl[blk - 1];
                size_t gi = (size_t)(rBase + r) * Fpad + f;
                cpa16(sb + off, shp + gi);
                cpa16(sb + 16384 + off, slp + gi);
            } else {
                *(uint4*)(sm + off) = make_uint4(0, 0, 0, 0);
                *(uint4*)(sm + off + 16384) = make_uint4(0, 0, 0, 0);
            }
        }
        #pragma unroll
        for (int i = 0; i < BG2; i++) {         // B: W, 32 k-rows x NT cols hi+lo
            int gid = t + 256 * i;
            int r, gc;
            if (NT == 128) { r = gid >> 4; gc = gid & 15; }
            else           { r = gid >> 3; gc = gid & 7; }
            size_t gi = (size_t)(kc * 32 + r) * NT + gc * 8;
            uint32_t d = sb + 32768 + (gc >> 3) * 8192 + swz(32 * s + r, gc & 7);
            cpa16(d, Wh + gi);
            cpa16(d + BL, Wl + gi);
        }
    };
    auto compute = [&](int s) {
        uint32_t aH = sb, aL = sb + 16384;
        #pragma unroll
        for (int ks = 0; ks < 32; ks += 16) {
            uint32_t a_h[2][4], a_l[2][4];
            #pragma unroll
            for (int ms = 0; ms < 2; ms++) {
                int row = wm * 32 + ms * 16 + (lane & 15);
                int gg = s * 4 + (ks >> 3) + (lane >> 4);
                uint32_t off = (uint32_t)(((row << 3) + (gg ^ (row & 7))) << 4);
                ldsm4(a_h[ms], aH + off);
                ldsm4(a_l[ms], aL + off);
            }
            uint32_t b_h[N8][2], b_l[N8][2];
            #pragma unroll
            for (int nf = 0; nf < NF; nf++) {
                int G = wn * (NT / 16) + nf * 2 + (lane >> 4);
                uint32_t off = sb + 32768 + (G >> 3) * 8192 + swz(32 * s + ks + (lane & 15), G & 7);
                uint32_t r4[4];
                ldsm4t(r4, off);
                b_h[2 * nf][0] = r4[0]; b_h[2 * nf][1] = r4[1];
                b_h[2 * nf + 1][0] = r4[2]; b_h[2 * nf + 1][1] = r4[3];
                ldsm4t(r4, off + BL);
                b_l[2 * nf][0] = r4[0]; b_l[2 * nf][1] = r4[1];
                b_l[2 * nf + 1][0] = r4[2]; b_l[2 * nf + 1][1] = r4[3];
            }
            #pragma unroll
            for (int ms = 0; ms < 2; ms++)
                #pragma unroll
                for (int n8 = 0; n8 < N8; n8++) {
                    mma16816(acc[ms][n8], a_h[ms], b_h[n8]);
                    mma16816(acc[ms][n8], a_h[ms], b_l[n8]);
                    mma16816(acc[ms][n8], a_l[ms], b_h[n8]);
                }
        }
    };

    stage(0, 0); CPA_COMMIT();
    for (int kc = 0; kc < KC; kc++) {
        if (kc < KC - 1) { stage(kc + 1, (kc + 1) & 1); CPA_COMMIT(); CPA_WAIT1(); }
        else CPA_WAIT0();
        __syncthreads();
        compute(kc & 1);
        __syncthreads();
    }

    float* hb = hsel ? g_h1 : g_h0;
    #pragma unroll
    for (int ms = 0; ms < 2; ms++)
        #pragma unroll
        for (int n8 = 0; n8 < N8; n8++) {
            int col = wn * (NT / 2) + n8 * 8 + (lane & 3) * 2;
            #pragma unroll
            for (int half = 0; half < 2; half++) {
                int r = rBase + wm * 32 + ms * 16 + (lane >> 2) + half * 8;
                float v0 = acc[ms][n8][half * 2] + bias[col];
                float v1 = acc[ms][n8][half * 2 + 1] + bias[col + 1];
                if (mode == 0) {
                    float2 o = make_float2(1.f / (1.f + expf(-v0)),
                                           1.f / (1.f + expf(-v1)));
                    *(float2*)(g_RU + (size_t)r * 128 + col) = o;
                } else {
                    float u0 = g_RU[(size_t)r * 128 + 64 + col];
                    float u1 = g_RU[(size_t)r * 128 + 64 + col + 1];
                    float h0v = hb[(size_t)r * 64 + col];
                    float h1v = hb[(size_t)r * 64 + col + 1];
                    float2 o = make_float2(u0 * h0v + (1.f - u0) * tanhf(v0),
                                           u1 * h1v + (1.f - u1) * tanhf(v1));
                    *(float2*)(hb + (size_t)r * 64 + col) = o;
                }
            }
        }
}

// ---------------- output projection + decoder feedback ----------------
__global__ void fcn_kernel(const float* __restrict__ fcnW,
                           const float* __restrict__ fcnb,
                           float* __restrict__ out) {
    int w = (blockIdx.x * blockDim.x + threadIdx.x) >> 5;
    int lane = threadIdx.x & 31;
    if (w >= ROWS) return;
    const float* hr = g_h1 + (size_t)w * 64;
    float s = hr[lane] * fcnW[lane] + hr[lane + 32] * fcnW[lane + 32];
    #pragma unroll
    for (int off = 16; off; off >>= 1) s += __shfl_down_sync(0xffffffffu, s, off);
    if (lane == 0) {
        int n = w >> 5, b = w & 31;
        float v = s + fcnb[0];
        out[b * NN + n] = v;
        g_xdec[w] = v;
    }
}

// ---------------- host ----------------
static void run_cell(const float* src, int xKind, int tstep, int Fx, int hsel,
                     int slotRu, int slotC, const float* bru, const float* bc,
                     int Fpad, int KC) {
    int L = 32 * Fpad;
    concat_full<<<(ROWS * Fpad + 255) / 256, 256>>>(src, Fpad, Fx, xKind, tstep, hsel);
    mm_diffuse<<<dim3(L / 128, 8, 4), 256, SMEMSZ>>>(0, L, Fpad);
    mm_w<128><<<256, 256, SMEMSZ>>>(slotRu, bru, Fpad, KC, 0, hsel);
    concat_rh<<<(ROWS * 64 + 255) / 256, 256>>>(Fpad, hsel);
    mm_diffuse<<<dim3(16, 8, 4), 256, SMEMSZ>>>(1, L, Fpad);
    mm_w<64><<<256, 256, 49152>>>(slotC, bc, Fpad, KC, 1, hsel);
}

extern "C" void kernel_launch(void* const* d_in, const int* in_sizes, int n_in,
                              void* d_out, int out_size) {
    (void)in_sizes; (void)n_in; (void)out_size;
    const float* adj    = (const float*)d_in[0];
    const float* source = (const float*)d_in[1];
    const float* W[8]   = {(const float*)d_in[3],  (const float*)d_in[5],
                           (const float*)d_in[7],  (const float*)d_in[9],
                           (const float*)d_in[11], (const float*)d_in[13],
                           (const float*)d_in[15], (const float*)d_in[17]};
    const float* B[8]   = {(const float*)d_in[4],  (const float*)d_in[6],
                           (const float*)d_in[8],  (const float*)d_in[10],
                           (const float*)d_in[12], (const float*)d_in[14],
                           (const float*)d_in[16], (const float*)d_in[18]};
    const float* fcnW = (const float*)d_in[19];
    const float* fcnb = (const float*)d_in[20];
    float* out = (float*)d_out;

    cudaFuncSetAttribute(mm_diffuse, cudaFuncAttributeMaxDynamicSharedMemorySize, SMEMSZ);
    cudaFuncSetAttribute(mm_w<128>, cudaFuncAttributeMaxDynamicSharedMemorySize, SMEMSZ);
    cudaFuncSetAttribute(mm_w<64>, cudaFuncAttributeMaxDynamicSharedMemorySize, 49152);
    cudaFuncSetAttribute(ssq_tc, cudaFuncAttributeMaxDynamicSharedMemorySize, SMEMSZ);

    zero_kernel<<<8192, 256>>>();
    rowsum_kernel<<<NN, 256>>>(adj);
    colsum_kernel<<<4, 256>>>(adj);
    build_supports<<<4096, 256>>>(adj);
    conv_hl<<<4096, 256>>>(0);
    conv_hl<<<4096, 256>>>(1);
    ssq_tc<<<dim3(8, 8, 2), 256, SMEMSZ>>>();

    const int cF[4]  = {66, 128, 65, 128};
    const int cFx[4] = {2, 64, 1, 64};
    const int cFp[4] = {72, 128, 72, 128};
    const int cKp[4] = {384, 640, 384, 640};
    for (int c = 0; c < 4; c++) {
        build_wpad<<<(cKp[c] * 128 + 255) / 256, 256>>>(W[c * 2],     c * 2,     cF[c], cFx[c], cFp[c], cKp[c], 128);
        build_wpad<<<(cKp[c] * 64  + 255) / 256, 256>>>(W[c * 2 + 1], c * 2 + 1, cF[c], cFx[c], cFp[c], cKp[c], 64);
    }

    for (int t = 0; t < TT; t++) {
        run_cell(source, 0, t, 2, 0, 0, 1, B[0], B[1], 72, 12);
        run_cell(source, 1, 0, 64, 1, 2, 3, B[2], B[3], 128, 20);
    }
    for (int t = 0; t < HORZ; t++) {
        run_cell(source, 2, 0, 1, 0, 4, 5, B[4], B[5], 72, 12);
        run_cell(source, 1, 0, 64, 1, 6, 7, B[6], B[7], 128, 20);
        fcn_kernel<<<4096, 256>>>(fcnW, fcnb, out + t * BB * NN);
    }
}

// round 16
// speedup vs baseline: 1.1874x; 1.0007x over previous
#include <cuda_runtime.h>
#include <cuda_bf16.h>
#include <math.h>
#include <stdint.h>

#define NN 1024
#define BB 32
#define TT 12
#define HORZ 12
#define ROWS (NN*BB)
#define SMEMSZ 65536

// ---------------- static device scratch ----------------
__device__ float g_Sf[2][NN * NN];
__device__ float g_rowsum[NN];
__device__ float g_colsum[NN];
__device__ __align__(16) __nv_bfloat16 g_Sh[2][NN * NN];
__device__ __align__(16) __nv_bfloat16 g_Sl[2][NN * NN];
__device__ __align__(16) __nv_bfloat16 g_SSh[2][NN * NN];
__device__ __align__(16) __nv_bfloat16 g_SSl[2][NN * NN];
__device__ __align__(16) __nv_bfloat16 g_Xh[NN * 4096];
__device__ __align__(16) __nv_bfloat16 g_Xl[NN * 4096];
__device__ __align__(16) __nv_bfloat16 g_Yh[4][NN * 4096];
__device__ __align__(16) __nv_bfloat16 g_Yl[4][NN * 4096];
__device__ __align__(16) __nv_bfloat16 g_Wph[8][640 * 128];
__device__ __align__(16) __nv_bfloat16 g_Wpl[8][640 * 128];
__device__ float g_RU[ROWS * 128];
__device__ float g_h0[ROWS * 64];
__device__ float g_h1[ROWS * 64];
__device__ float g_xdec[ROWS];

// ---------------- helpers ----------------
__device__ __forceinline__ uint32_t smem_u32(const void* p) {
    return (uint32_t)__cvta_generic_to_shared(p);
}
__device__ __forceinline__ void ldsm4(uint32_t* r, uint32_t addr) {
    asm volatile("ldmatrix.sync.aligned.m8n8.x4.shared.b16 {%0,%1,%2,%3}, [%4];"
                 : "=r"(r[0]), "=r"(r[1]), "=r"(r[2]), "=r"(r[3]) : "r"(addr));
}
__device__ __forceinline__ void ldsm4t(uint32_t* r, uint32_t addr) {
    asm volatile("ldmatrix.sync.aligned.m8n8.x4.trans.shared.b16 {%0,%1,%2,%3}, [%4];"
                 : "=r"(r[0]), "=r"(r[1]), "=r"(r[2]), "=r"(r[3]) : "r"(addr));
}
__device__ __forceinline__ void mma16816(float* d, const uint32_t* a, const uint32_t* b) {
    asm volatile("mma.sync.aligned.m16n8k16.row.col.f32.bf16.bf16.f32 "
                 "{%0,%1,%2,%3},{%4,%5,%6,%7},{%8,%9},{%0,%1,%2,%3};"
                 : "+f"(d[0]), "+f"(d[1]), "+f"(d[2]), "+f"(d[3])
                 : "r"(a[0]), "r"(a[1]), "r"(a[2]), "r"(a[3]), "r"(b[0]), "r"(b[1]));
}
__device__ __forceinline__ void cpa16(uint32_t dst, const void* src) {
    asm volatile("cp.async.cg.shared.global [%0], [%1], 16;" :: "r"(dst), "l"(src));
}
#define CPA_COMMIT() asm volatile("cp.async.commit_group;" ::: "memory")
#define CPA_WAIT1()  asm volatile("cp.async.wait_group 1;" ::: "memory")
#define CPA_WAIT0()  asm volatile("cp.async.wait_group 0;" ::: "memory")
__device__ __forceinline__ uint32_t swz(int row, int g) {
    return (uint32_t)(((row << 3) + (g ^ (row & 7))) << 4);
}

// ---------------- mega init: zero + rowsum + colsum + all W pads in ONE launch ----------------
// blocks [0,8192): zero h0/h1/xdec
// blocks [8192,9216): rowsum (n = b-8192)
// blocks [9216,9220): colsum
// blocks [9220,9220+8*320): build_wpad slot = (b-9220)/320
__global__ void mega_init(const float* __restrict__ adj,
                          const float* __restrict__ W0, const float* __restrict__ W1,
                          const float* __restrict__ W2, const float* __restrict__ W3,
                          const float* __restrict__ W4, const float* __restrict__ W5,
                          const float* __restrict__ W6, const float* __restrict__ W7) {
    int b = blockIdx.x, t = threadIdx.x;
    if (b < 8192) {
        int i = b * 256 + t;
        if (i < ROWS * 64) { g_h0[i] = 0.f; g_h1[i] = 0.f; }
        if (i < ROWS) g_xdec[i] = 0.f;
    } else if (b < 9216) {
        int n = b - 8192;
        float s = 0.f;
        for (int j = t; j < NN; j += 256) s += adj[n * NN + j];
        __shared__ float sh[256];
        sh[t] = s; __syncthreads();
        for (int o = 128; o; o >>= 1) {
            if (t < o) sh[t] += sh[t + o];
            __syncthreads();
        }
        if (t == 0) g_rowsum[n] = sh[0];
    } else if (b < 9220) {
        int c = (b - 9216) * 256 + t;
        float s = 0.f;
        #pragma unroll 8
        for (int r = 0; r < NN; r++) s += adj[r * NN + c];
        g_colsum[c] = s;
    } else {
        int bb = b - 9220;
        int slot = bb / 320, bi = bb % 320;
        const int cF[4]  = {66, 128, 65, 128};
        const int cFx[4] = {2, 64, 1, 64};
        const int cFp[4] = {72, 128, 72, 128};
        const int cKp[4] = {384, 640, 384, 640};
        int c = slot >> 1;
        int F = cF[c], Fx = cFx[c], Fpad = cFp[c], Kpad = cKp[c];
        int NT = (slot & 1) ? 64 : 128;
        const float* W;
        switch (slot) {
            case 0: W = W0; break; case 1: W = W1; break;
            case 2: W = W2; break; case 3: W = W3; break;
            case 4: W = W4; break; case 5: W = W5; break;
            case 6: W = W6; break; default: W = W7; break;
        }
        int idx = bi * 256 + t;
        if (idx >= Kpad * NT) return;
        int kp = idx / NT, o = idx % NT;
        float v = 0.f;
        if (kp < 5 * Fpad) {
            int blk = kp / Fpad, f = kp - blk * Fpad;
            if (f < 64) v = W[(size_t)(blk * F + Fx + f) * NT + o];
            else if (f < 64 + Fx) v = W[(size_t)(blk * F + f - 64) * NT + o];
        }
        __nv_bfloat16 hi = __float2bfloat16(v);
        g_Wph[slot][idx] = hi;
        g_Wpl[slot][idx] = __float2bfloat16(v - __bfloat162float(hi));
    }
}

__global__ void build_supports(const float* __restrict__ adj) {
    int idx = blockIdx.x * 256 + threadIdx.x;
    int m = idx >> 10, n = idx & 1023;
    g_Sf[0][idx] = adj[n * NN + m] / fmaxf(g_rowsum[n], 1e-8f);
    g_Sf[1][idx] = adj[m * NN + n] / fmaxf(g_colsum[n], 1e-8f);
}
__global__ void conv_hl2() {
    int sel = blockIdx.y;
    int idx = blockIdx.x * 256 + threadIdx.x;
    float v = g_Sf[sel][idx];
    __nv_bfloat16 hi = __float2bfloat16(v);
    g_Sh[sel][idx] = hi;
    g_Sl[sel][idx] = __float2bfloat16(v - __bfloat162float(hi));
}

// ---------------- tensor-core SS = 2*S@S - I, fused hi/lo output ----------------
__global__ __launch_bounds__(256, 2) void ssq_tc() {
    extern __shared__ char sm[];
    const uint32_t sb = smem_u32(sm);
    const int t = threadIdx.x, warp = t >> 5, lane = t & 31;
    const int wm = warp & 3, wn = warp >> 2;
    const int z = blockIdx.z;
    const __nv_bfloat16* Sh = g_Sh[z];
    const __nv_bfloat16* Sl = g_Sl[z];
    const int mBase = blockIdx.y * 128;
    const int jt = blockIdx.x;

    float acc[2][8][4];
    #pragma unroll
    for (int a = 0; a < 2; a++)
        #pragma unroll
        for (int b = 0; b < 8; b++)
            #pragma unroll
            for (int c = 0; c < 4; c++) acc[a][b][c] = 0.f;

    auto stage = [&](int kc, int s) {
        #pragma unroll
        for (int i = 0; i < 2; i++) {
            int gid = t + 256 * i;
            int r = gid >> 2, g = gid & 3;
            size_t gi = (size_t)(mBase + r) * NN + kc * 32 + g * 8;
            uint32_t off = (uint32_t)(((r << 3) + ((s * 4 + g) ^ (r & 7))) << 4);
            cpa16(sb + off, Sh + gi);
            cpa16(sb + 16384 + off, Sl + gi);
        }
        #pragma unroll
        for (int i = 0; i < 2; i++) {
            int gid = t + 256 * i;
            int r = gid >> 4, gc = gid & 15;
            size_t gi = (size_t)(kc * 32 + r) * NN + jt * 128 + gc * 8;
            uint32_t d = sb + 32768 + (gc >> 3) * 8192 + swz(32 * s + r, gc & 7);
            cpa16(d, Sh + gi);
            cpa16(d + 16384, Sl + gi);
        }
    };
    auto compute = [&](int s) {
        uint32_t aH = sb, aL = sb + 16384;
        uint32_t bH = sb + 32768 + wn * 8192, bL = bH + 16384;
        #pragma unroll
        for (int ks = 0; ks < 32; ks += 16) {
            uint32_t a_h[2][4], a_l[2][4];
            #pragma unroll
            for (int ms = 0; ms < 2; ms++) {
                int row = wm * 32 + ms * 16 + (lane & 15);
                int gg = s * 4 + (ks >> 3) + (lane >> 4);
                uint32_t off = (uint32_t)(((row << 3) + (gg ^ (row & 7))) << 4);
                ldsm4(a_h[ms], aH + off);
                ldsm4(a_l[ms], aL + off);
            }
            uint32_t b_h[8][2], b_l[8][2];
            #pragma unroll
            for (int nf = 0; nf < 4; nf++) {
                uint32_t off = swz(32 * s + ks + (lane & 15), nf * 2 + (lane >> 4));
                uint32_t r4[4];
                ldsm4t(r4, bH + off);
                b_h[2 * nf][0] = r4[0]; b_h[2 * nf][1] = r4[1];
                b_h[2 * nf + 1][0] = r4[2]; b_h[2 * nf + 1][1] = r4[3];
                ldsm4t(r4, bL + off);
                b_l[2 * nf][0] = r4[0]; b_l[2 * nf][1] = r4[1];
                b_l[2 * nf + 1][0] = r4[2]; b_l[2 * nf + 1][1] = r4[3];
            }
            #pragma unroll
            for (int ms = 0; ms < 2; ms++)
                #pragma unroll
                for (int n8 = 0; n8 < 8; n8++) {
                    mma16816(acc[ms][n8], a_h[ms], b_h[n8]);
                    mma16816(acc[ms][n8], a_h[ms], b_l[n8]);
                    mma16816(acc[ms][n8], a_l[ms], b_h[n8]);
                }
        }
    };

    stage(0, 0); CPA_COMMIT();
    for (int kc = 0; kc < 32; kc++) {
        if (kc < 31) { stage(kc + 1, (kc + 1) & 1); CPA_COMMIT(); CPA_WAIT1(); }
        else CPA_WAIT0();
        __syncthreads();
        compute(kc & 1);
        __syncthreads();
    }

    #pragma unroll
    for (int ms = 0; ms < 2; ms++)
        #pragma unroll
        for (int n8 = 0; n8 < 8; n8++) {
            int col = wn * 64 + n8 * 8 + (lane & 3) * 2;
            int j = jt * 128 + col;
            #pragma unroll
            for (int half = 0; half < 2; half++) {
                int m = mBase + wm * 32 + ms * 16 + (lane >> 2) + half * 8;
                float v0 = 2.f * acc[ms][n8][half * 2]     - ((m == j)     ? 1.f : 0.f);
                float v1 = 2.f * acc[ms][n8][half * 2 + 1] - ((m == j + 1) ? 1.f : 0.f);
                __nv_bfloat162 hv, lv;
                hv.x = __float2bfloat16(v0); hv.y = __float2bfloat16(v1);
                lv.x = __float2bfloat16(v0 - __bfloat162float(hv.x));
                lv.y = __float2bfloat16(v1 - __bfloat162float(hv.y));
                *(__nv_bfloat162*)(g_SSh[z] + (size_t)m * NN + j) = hv;
                *(__nv_bfloat162*)(g_SSl[z] + (size_t)m * NN + j) = lv;
            }
        }
}

// ---------------- concat: build X (bf16 hi/lo), layout [h|x|pad] ----------------
__global__ void concat_full(const float* __restrict__ src, int Fpad, int Fx,
                            int xKind, int tstep, int hsel) {
    int idx = blockIdx.x * 256 + threadIdx.x;
    if (idx >= ROWS * Fpad) return;
    int f = idx % Fpad, nb = idx / Fpad;
    float v = 0.f;
    if (f < 64) v = (hsel ? g_h1 : g_h0)[nb * 64 + f];
    else if (f < 64 + Fx) {
        int xi = f - 64;
        if (xKind == 0) { int n = nb >> 5, b = nb & 31; v = src[((b * TT + tstep) * NN + n) * 2 + xi]; }
        else if (xKind == 1) v = g_h0[nb * 64 + xi];
        else v = g_xdec[nb];
    }
    __nv_bfloat16 hi = __float2bfloat16(v);
    g_Xh[idx] = hi;
    g_Xl[idx] = __float2bfloat16(v - __bfloat162float(hi));
}
__global__ void concat_rh(int Fpad, int hsel) {
    int idx = blockIdx.x * 256 + threadIdx.x;
    if (idx >= ROWS * 64) return;
    int f = idx & 63, nb = idx >> 6;
    float v = (hsel ? g_h1 : g_h0)[idx] * g_RU[nb * 128 + f];
    __nv_bfloat16 hi = __float2bfloat16(v);
    g_Xh[(size_t)nb * Fpad + f] = hi;
    g_Xl[(size_t)nb * Fpad + f] = __float2bfloat16(v - __bfloat162float(hi));
}

// ---------------- diffusion GEMM: Y[z] = M[z] @ X, both hi/lo, 3 MMAs ----------------
__global__ __launch_bounds__(256, 2) void mm_diffuse(int win, int L, int Fpad) {
    extern __shared__ char sm[];
    const uint32_t sb = smem_u32(sm);
    const int t = threadIdx.x, warp = t >> 5, lane = t & 31;
    const int wm = warp & 3, wn = warp >> 2;
    const int z = blockIdx.z;
    const __nv_bfloat16* Agh = (z & 1) ? g_SSh[z >> 1] : g_Sh[z >> 1];
    const __nv_bfloat16* Agl = (z & 1) ? g_SSl[z >> 1] : g_Sl[z >> 1];
    __nv_bfloat16* Yh = g_Yh[z];
    __nv_bfloat16* Yl = g_Yl[z];
    const int mBase = blockIdx.y * 128;
    const int jt = blockIdx.x;

    float acc[2][8][4];
    #pragma unroll
    for (int a = 0; a < 2; a++)
        #pragma unroll
        for (int b = 0; b < 8; b++)
            #pragma unroll
            for (int c = 0; c < 4; c++) acc[a][b][c] = 0.f;

    auto stage = [&](int kc, int s) {
        #pragma unroll
        for (int i = 0; i < 2; i++) {
            int gid = t + 256 * i;
            int r = gid >> 2, g = gid & 3;
            size_t gi = (size_t)(mBase + r) * NN + kc * 32 + g * 8;
            uint32_t off = (uint32_t)(((r << 3) + ((s * 4 + g) ^ (r & 7))) << 4);
            cpa16(sb + off, Agh + gi);
            cpa16(sb + 16384 + off, Agl + gi);
        }
        #pragma unroll
        for (int i = 0; i < 2; i++) {
            int gid = t + 256 * i;
            int r = gid >> 4, gc = gid & 15;
            int j = win ? ((jt * 2 + (gc >> 3)) * Fpad + (gc & 7) * 8)
                        : (jt * 128 + gc * 8);
            size_t gi = (size_t)(kc * 32 + r) * L + j;
            uint32_t d = sb + 32768 + (gc >> 3) * 8192 + swz(32 * s + r, gc & 7);
            cpa16(d, g_Xh + gi);
            cpa16(d + 16384, g_Xl + gi);
        }
    };
    auto compute = [&](int s) {
        uint32_t aH = sb, aL = sb + 16384;
        uint32_t bH = sb + 32768 + wn * 8192, bL = bH + 16384;
        #pragma unroll
        for (int ks = 0; ks < 32; ks += 16) {
            uint32_t a_h[2][4], a_l[2][4];
            #pragma unroll
            for (int ms = 0; ms < 2; ms++) {
                int row = wm * 32 + ms * 16 + (lane & 15);
                int gg = s * 4 + (ks >> 3) + (lane >> 4);
                uint32_t off = (uint32_t)(((row << 3) + (gg ^ (row & 7))) << 4);
                ldsm4(a_h[ms], aH + off);
                ldsm4(a_l[ms], aL + off);
            }
            uint32_t b_h[8][2], b_l[8][2];
            #pragma unroll
            for (int nf = 0; nf < 4; nf++) {
                uint32_t off = swz(32 * s + ks + (lane & 15), nf * 2 + (lane >> 4));
                uint32_t r4[4];
                ldsm4t(r4, bH + off);
                b_h[2 * nf][0] = r4[0]; b_h[2 * nf][1] = r4[1];
                b_h[2 * nf + 1][0] = r4[2]; b_h[2 * nf + 1][1] = r4[3];
                ldsm4t(r4, bL + off);
                b_l[2 * nf][0] = r4[0]; b_l[2 * nf][1] = r4[1];
                b_l[2 * nf + 1][0] = r4[2]; b_l[2 * nf + 1][1] = r4[3];
            }
            #pragma unroll
            for (int ms = 0; ms < 2; ms++)
                #pragma unroll
                for (int n8 = 0; n8 < 8; n8++) {
                    mma16816(acc[ms][n8], a_h[ms], b_h[n8]);
                    mma16816(acc[ms][n8], a_h[ms], b_l[n8]);
                    mma16816(acc[ms][n8], a_l[ms], b_h[n8]);
                }
        }
    };

    stage(0, 0); CPA_COMMIT();
    for (int kc = 0; kc < 32; kc++) {
        if (kc < 31) { stage(kc + 1, (kc + 1) & 1); CPA_COMMIT(); CPA_WAIT1(); }
        else CPA_WAIT0();
        __syncthreads();
        compute(kc & 1);
        __syncthreads();
    }

    #pragma unroll
    for (int ms = 0; ms < 2; ms++)
        #pragma unroll
        for (int n8 = 0; n8 < 8; n8++) {
            int col = wn * 64 + n8 * 8 + (lane & 3) * 2;
            int j = win ? ((jt * 2 + (col >> 6)) * Fpad + (col & 63))
                        : (jt * 128 + col);
            #pragma unroll
            for (int half = 0; half < 2; half++) {
                int m = mBase + wm * 32 + ms * 16 + (lane >> 2) + half * 8;
                float v0 = acc[ms][n8][half * 2], v1 = acc[ms][n8][half * 2 + 1];
                __nv_bfloat162 hv, lv;
                hv.x = __float2bfloat16(v0); hv.y = __float2bfloat16(v1);
                lv.x = __float2bfloat16(v0 - __bfloat162float(hv.x));
                lv.y = __float2bfloat16(v1 - __bfloat162float(hv.y));
                *(__nv_bfloat162*)(Yh + (size_t)m * L + j) = hv;
                *(__nv_bfloat162*)(Yl + (size_t)m * L + j) = lv;
            }
        }
}

// ---------------- W projection: Z(hi/lo) @ W(hi/lo), 3 MMAs, fused GRU epilogue ----------------
template<int NT>
__global__ __launch_bounds__(256, 2) void mm_w(int slot, const float* __restrict__ bias,
                                               int Fpad, int KC, int mode, int hsel) {
    extern __shared__ char sm[];
    const uint32_t sb = smem_u32(sm);
    const int t = threadIdx.x, warp = t >> 5, lane = t & 31;
    const int wm = warp & 3, wn = warp >> 2;
    const int rBase = blockIdx.x * 128;
    const __nv_bfloat16* Wh = g_Wph[slot];
    const __nv_bfloat16* Wl = g_Wpl[slot];
    const int F5 = 5 * Fpad;
    constexpr int N8 = NT / 16, NF = NT / 32, BG2 = NT / 64;
    constexpr uint32_t BL = (NT == 128) ? 16384 : 8192;

    float acc[2][N8][4];
    #pragma unroll
    for (int a = 0; a < 2; a++)
        #pragma unroll
        for (int b = 0; b < N8; b++)
            #pragma unroll
            for (int c = 0; c < 4; c++) acc[a][b][c] = 0.f;

    auto stage = [&](int kc, int s) {
        #pragma unroll
        for (int i = 0; i < 2; i++) {
            int gid = t + 256 * i;
            int r = gid >> 2, g = gid & 3;
            int kp = kc * 32 + g * 8;
            uint32_t off = (uint32_t)(((r << 3) + ((s * 4 + g) ^ (r & 7))) << 4);
            if (kp < F5) {
                int blk = kp / Fpad, f = kp - blk * Fpad;
                const __nv_bfloat16* shp = (blk == 0) ? g_Xh : g_Yh[blk - 1];
                const __nv_bfloat16* slp = (blk == 0) ? g_Xl : g_Yl[blk - 1];
                size_t gi = (size_t)(rBase + r) * Fpad + f;
                cpa16(sb + off, shp + gi);
                cpa16(sb + 16384 + off, slp + gi);
            } else {
                *(uint4*)(sm + off) = make_uint4(0, 0, 0, 0);
                *(uint4*)(sm + off + 16384) = make_uint4(0, 0, 0, 0);
            }
        }
        #pragma unroll
        for (int i = 0; i < BG2; i++) {
            int gid = t + 256 * i;
            int r, gc;
            if (NT == 128) { r = gid >> 4; gc = gid & 15; }
            else           { r = gid >> 3; gc = gid & 7; }
            size_t gi = (size_t)(kc * 32 + r) * NT + gc * 8;
            uint32_t d = sb + 32768 + (gc >> 3) * 8192 + swz(32 * s + r, gc & 7);
            cpa16(d, Wh + gi);
            cpa16(d + BL, Wl + gi);
        }
    };
    auto compute = [&](int s) {
        uint32_t aH = sb, aL = sb + 16384;
        #pragma unroll
        for (int ks = 0; ks < 32; ks += 16) {
            uint32_t a_h[2][4], a_l[2][4];
            #pragma unroll
            for (int ms = 0; ms < 2; ms++) {
                int row = wm * 32 + ms * 16 + (lane & 15);
                int gg = s * 4 + (ks >> 3) + (lane >> 4);
                uint32_t off = (uint32_t)(((row << 3) + (gg ^ (row & 7))) << 4);
                ldsm4(a_h[ms], aH + off);
                ldsm4(a_l[ms], aL + off);
            }
            uint32_t b_h[N8][2], b_l[N8][2];
            #pragma unroll
            for (int nf = 0; nf < NF; nf++) {
                int G = wn * (NT / 16) + nf * 2 + (lane >> 4);
                uint32_t off = sb + 32768 + (G >> 3) * 8192 + swz(32 * s + ks + (lane & 15), G & 7);
                uint32_t r4[4];
                ldsm4t(r4, off);
                b_h[2 * nf][0] = r4[0]; b_h[2 * nf][1] = r4[1];
                b_h[2 * nf + 1][0] = r4[2]; b_h[2 * nf + 1][1] = r4[3];
                ldsm4t(r4, off + BL);
                b_l[2 * nf][0] = r4[0]; b_l[2 * nf][1] = r4[1];
                b_l[2 * nf + 1][0] = r4[2]; b_l[2 * nf + 1][1] = r4[3];
            }
            #pragma unroll
            for (int ms = 0; ms < 2; ms++)
                #pragma unroll
                for (int n8 = 0; n8 < N8; n8++) {
                    mma16816(acc[ms][n8], a_h[ms], b_h[n8]);
                    mma16816(acc[ms][n8], a_h[ms], b_l[n8]);
                    mma16816(acc[ms][n8], a_l[ms], b_h[n8]);
                }
        }
    };

    stage(0, 0); CPA_COMMIT();
    for (int kc = 0; kc < KC; kc++) {
        if (kc < KC - 1) { stage(kc + 1, (kc + 1) & 1); CPA_COMMIT(); CPA_WAIT1(); }
        else CPA_WAIT0();
        __syncthreads();
        compute(kc & 1);
        __syncthreads();
    }

    float* hb = hsel ? g_h1 : g_h0;
    #pragma unroll
    for (int ms = 0; ms < 2; ms++)
        #pragma unroll
        for (int n8 = 0; n8 < N8; n8++) {
            int col = wn * (NT / 2) + n8 * 8 + (lane & 3) * 2;
            #pragma unroll
            for (int half = 0; half < 2; half++) {
                int r = rBase + wm * 32 + ms * 16 + (lane >> 2) + half * 8;
                float v0 = acc[ms][n8][half * 2] + bias[col];
                float v1 = acc[ms][n8][half * 2 + 1] + bias[col + 1];
                if (mode == 0) {
                    float2 o = make_float2(1.f / (1.f + expf(-v0)),
                                           1.f / (1.f + expf(-v1)));
                    *(float2*)(g_RU + (size_t)r * 128 + col) = o;
                } else {
                    float u0 = g_RU[(size_t)r * 128 + 64 + col];
                    float u1 = g_RU[(size_t)r * 128 + 64 + col + 1];
                    float h0v = hb[(size_t)r * 64 + col];
                    float h1v = hb[(size_t)r * 64 + col + 1];
                    float2 o = make_float2(u0 * h0v + (1.f - u0) * tanhf(v0),
                                           u1 * h1v + (1.f - u1) * tanhf(v1));
                    *(float2*)(hb + (size_t)r * 64 + col) = o;
                }
            }
        }
}

// ---------------- output projection + decoder feedback ----------------
__global__ void fcn_kernel(const float* __restrict__ fcnW,
                           const float* __restrict__ fcnb,
                           float* __restrict__ out) {
    int w = (blockIdx.x * blockDim.x + threadIdx.x) >> 5;
    int lane = threadIdx.x & 31;
    if (w >= ROWS) return;
    const float* hr = g_h1 + (size_t)w * 64;
    float s = hr[lane] * fcnW[lane] + hr[lane + 32] * fcnW[lane + 32];
    #pragma unroll
    for (int off = 16; off; off >>= 1) s += __shfl_down_sync(0xffffffffu, s, off);
    if (lane == 0) {
        int n = w >> 5, b = w & 31;
        float v = s + fcnb[0];
        out[b * NN + n] = v;
        g_xdec[w] = v;
    }
}

// ---------------- host ----------------
static void run_cell(const float* src, int xKind, int tstep, int Fx, int hsel,
                     int slotRu, int slotC, const float* bru, const float* bc,
                     int Fpad, int KC) {
    int L = 32 * Fpad;
    concat_full<<<(ROWS * Fpad + 255) / 256, 256>>>(src, Fpad, Fx, xKind, tstep, hsel);
    mm_diffuse<<<dim3(L / 128, 8, 4), 256, SMEMSZ>>>(0, L, Fpad);
    mm_w<128><<<256, 256, SMEMSZ>>>(slotRu, bru, Fpad, KC, 0, hsel);
    concat_rh<<<(ROWS * 64 + 255) / 256, 256>>>(Fpad, hsel);
    mm_diffuse<<<dim3(16, 8, 4), 256, SMEMSZ>>>(1, L, Fpad);
    mm_w<64><<<256, 256, 49152>>>(slotC, bc, Fpad, KC, 1, hsel);
}

extern "C" void kernel_launch(void* const* d_in, const int* in_sizes, int n_in,
                              void* d_out, int out_size) {
    (void)in_sizes; (void)n_in; (void)out_size;
    const float* adj    = (const float*)d_in[0];
    const float* source = (const float*)d_in[1];
    const float* W[8]   = {(const float*)d_in[3],  (const float*)d_in[5],
                           (const float*)d_in[7],  (const float*)d_in[9],
                           (const float*)d_in[11], (const float*)d_in[13],
                           (const float*)d_in[15], (const float*)d_in[17]};
    const float* B[8]   = {(const float*)d_in[4],  (const float*)d_in[6],
                           (const float*)d_in[8],  (const float*)d_in[10],
                           (const float*)d_in[12], (const float*)d_in[14],
                           (const float*)d_in[16], (const float*)d_in[18]};
    const float* fcnW = (const float*)d_in[19];
    const float* fcnb = (const float*)d_in[20];
    float* out = (float*)d_out;

    cudaFuncSetAttribute(mm_diffuse, cudaFuncAttributeMaxDynamicSharedMemorySize, SMEMSZ);
    cudaFuncSetAttribute(mm_w<128>, cudaFuncAttributeMaxDynamicSharedMemorySize, SMEMSZ);
    cudaFuncSetAttribute(mm_w<64>, cudaFuncAttributeMaxDynamicSharedMemorySize, 49152);
    cudaFuncSetAttribute(ssq_tc, cudaFuncAttributeMaxDynamicSharedMemorySize, SMEMSZ);

    // mega init: zero + rowsum + colsum + 8x build_wpad, one launch
    mega_init<<<9220 + 8 * 320, 256>>>(adj, W[0], W[1], W[2], W[3], W[4], W[5], W[6], W[7]);
    build_supports<<<4096, 256>>>(adj);
    conv_hl2<<<dim3(4096, 2), 256>>>();
    ssq_tc<<<dim3(8, 8, 2), 256, SMEMSZ>>>();

    for (int t = 0; t < TT; t++) {
        run_cell(source, 0, t, 2, 0, 0, 1, B[0], B[1], 72, 12);
        run_cell(source, 1, 0, 64, 1, 2, 3, B[2], B[3], 128, 20);
    }
    for (int t = 0; t < HORZ; t++) {
        run_cell(source, 2, 0, 1, 0, 4, 5, B[4], B[5], 72, 12);
        run_cell(source, 1, 0, 64, 1, 6, 7, B[6], B[7], 128, 20);
        fcn_kernel<<<4096, 256>>>(fcnW, fcnb, out + t * BB * NN);
    }
}